// round 7
// baseline (speedup 1.0000x reference)
#include <cuda_runtime.h>

// Exact L-inf nearest neighbor.
// build_k : one block bins B into (a) a CSR grid (exact fallback) and
//           (b) a fixed-slot 66x66 halo grid, K=4 float4 slots/cell,
//           empty slots sentineled (x=1e30), overflow cells marked.
// query_k : 8 lanes/query. Uniform fast path: scan exactly 36 slots
//           (3x3 cells, 12 contiguous float4 per row) with u64 pack+min,
//           3-level shfl reduce, geometric wall bound. Overflow marker or
//           unresolved bound -> exact expanding-ring CSR fallback.
// u64 pack: dist_bits<<32 | idx<<20 | flag19 | pos(0..14). min() IS the
// lexicographic (d, idx) argmin -> exact jnp.argmin tie semantics.

#define G      64
#define GH     (G + 2)                   // halo grid
#define NCELL  (G * G)
#define NCELLH (GH * GH)
#define K      4
#define X0     (-4.5f)
#define EXT    9.0f
#define H      (EXT / (float)G)          // 0.140625, exact
#define INVH   ((float)G / EXT)
#define MAXPTS 16384
#define LPQ    8
#define SENT   1e30f
#define OVF    2e30f

__device__ int    g_off[NCELL + 1];      // CSR offsets (interior grid)
__device__ float4 g_pts[MAXPTS];         // CSR points (x, y, idx_bits, 0)
__device__ float4 g_slot[NCELLH * K];    // fixed slots (halo grid), zero-init

__device__ __forceinline__ int cell_coord(float v) {
    int c = __float2int_rd((v - X0) * INVH);
    return min(max(c, 0), G - 1);
}

// ---------------- build: one block ----------------
__global__ void __launch_bounds__(1024)
build_k(const float* __restrict__ B, int N)
{
    __shared__ int s_cnt[NCELL];
    __shared__ int s_off[NCELL];
    __shared__ int s_wsum[32];
    __shared__ int s_total;

    const int t = threadIdx.x;
    for (int c = t; c < NCELL; c += 1024) s_cnt[c] = 0;
    __syncthreads();

    float px[4], py[4]; int pcell[4]; int np = 0;
    for (int n = t; n < N; n += 1024) {
        float x = B[n], y = B[N + n];
        int c = cell_coord(y) * G + cell_coord(x);
        px[np] = x; py[np] = y; pcell[np] = c; ++np;
        atomicAdd(&s_cnt[c], 1);
    }
    __syncthreads();

    // exclusive scan over 4096 cells
    const int base = t * (NCELL / 1024);
    int l0 = s_cnt[base+0], l1 = s_cnt[base+1], l2 = s_cnt[base+2], l3 = s_cnt[base+3];
    int tot = l0 + l1 + l2 + l3;
    const int lane = t & 31, wid = t >> 5;
    int v = tot;
    #pragma unroll
    for (int m = 1; m < 32; m <<= 1) {
        int u = __shfl_up_sync(0xffffffffu, v, m);
        if (lane >= m) v += u;
    }
    if (lane == 31) s_wsum[wid] = v;
    __syncthreads();
    if (wid == 0) {
        int w = s_wsum[lane];
        #pragma unroll
        for (int m = 1; m < 32; m <<= 1) {
            int u = __shfl_up_sync(0xffffffffu, w, m);
            if (lane >= m) w += u;
        }
        s_wsum[lane] = w;
    }
    __syncthreads();
    int excl = v - tot + (wid ? s_wsum[wid - 1] : 0);
    s_off[base+0] = excl;
    s_off[base+1] = excl + l0;
    s_off[base+2] = excl + l0 + l1;
    s_off[base+3] = excl + l0 + l1 + l2;
    s_cnt[base+0] = 0; s_cnt[base+1] = 0; s_cnt[base+2] = 0; s_cnt[base+3] = 0;
    if (t == 1023) s_total = excl + tot;
    __syncthreads();

    for (int c = t; c < NCELL; c += 1024) g_off[c] = s_off[c];
    if (t == 1023) g_off[NCELL] = s_total;

    // sentinel / overflow markers on the halo slot grid
    for (int hc = t; hc < NCELLH; hc += 1024) {
        int hi = hc % GH, hj = hc / GH;
        bool interior = (hi >= 1 && hi <= G) && (hj >= 1 && hj <= G);
        int cnt = 0;
        if (interior) {
            int c = (hj - 1) * G + (hi - 1);
            int nxt = (c == NCELL - 1) ? s_total : s_off[c + 1];
            cnt = nxt - s_off[c];
        }
        if (cnt > K) {
            g_slot[hc * K + (K - 1)].x = OVF;        // overflow marker
        } else {
            for (int s = cnt; s < K; ++s) g_slot[hc * K + s].x = SENT;
        }
    }

    // scatter: CSR always; slot if rank fits
    for (int k = 0; k < np; ++k) {
        int c = pcell[k];
        int n = t + (k << 10);
        int rank = atomicAdd(&s_cnt[c], 1);
        float4 pt = make_float4(px[k], py[k], __int_as_float(n), 0.0f);
        g_pts[s_off[c] + rank] = pt;
        int nxt = (c == NCELL - 1) ? s_total : s_off[c + 1];
        int cnt = nxt - s_off[c];
        int lim = (cnt > K) ? (K - 1) : K;
        if (rank < lim) {
            int hi = (c % G) + 1, hj = (c / G) + 1;
            g_slot[(hj * GH + hi) * K + rank] = pt;
        }
    }
}

// ---------------- query ----------------
__device__ __forceinline__ void csr_cell(int c, float ax, float ay,
                                         unsigned long long& best)
{
    int s = __ldg(&g_off[c]);
    int e = __ldg(&g_off[c + 1]);
    for (int p = s; p < e; ++p) {
        float4 pt = __ldg(&g_pts[p]);
        float dx = ax - pt.x, dy = ay - pt.y;
        float d  = fmaxf(fabsf(dx), fabsf(dy));
        unsigned pay = (__float_as_uint(pt.z) << 20) | 0x80000u | (unsigned)p;
        unsigned long long cand =
            (((unsigned long long)__float_as_uint(d)) << 32) | pay;
        best = min(best, cand);
    }
}

__global__ void __launch_bounds__(256)
query_k(const float* __restrict__ A, float* __restrict__ out, int Q)
{
    const int tid  = blockIdx.x * 256 + threadIdx.x;
    const int q    = tid >> 3;
    const int lane = tid & 7;
    if (q >= Q) return;

    const unsigned gmask = 0xFFu << (threadIdx.x & 24);

    const float ax = __ldg(&A[2 * q]);
    const float ay = __ldg(&A[2 * q + 1]);
    const int cx = cell_coord(ax);
    const int cy = cell_coord(ay);

    unsigned long long best = 0xFFFFFFFFFFFFFFFFull;

    // ---- uniform fast path: 36 slots over 3 rows of 12 contiguous float4 ----
    {
        const int b0 = ((cy + 0) * GH + cx) * K;   // j = cy-1 (halo coords)
        const int b1 = ((cy + 1) * GH + cx) * K;   // j = cy
        const int b2 = ((cy + 2) * GH + cx) * K;   // j = cy+1
        #pragma unroll
        for (int k = 0; k < 5; ++k) {
            int s = lane + k * 8;
            if (s >= 36) s -= 36;                  // wrap: rescan is harmless
            int row = s / 12;
            int col = s - row * 12;
            int gi  = (row == 0 ? b0 : (row == 1 ? b1 : b2)) + col;
            float4 pt = __ldg(&g_slot[gi]);
            float dx = ax - pt.x, dy = ay - pt.y;
            float d  = fmaxf(fabsf(dx), fabsf(dy));
            unsigned pay = (__float_as_uint(pt.z) << 20) | (unsigned)gi;
            unsigned long long cand =
                (((unsigned long long)__float_as_uint(d)) << 32) | pay;
            cand = (pt.x == OVF) ? 1ull : cand;    // overflow marker wins min
            best = min(best, cand);
        }
    }
    #pragma unroll
    for (int m = 4; m >= 1; m >>= 1)
        best = min(best, __shfl_xor_sync(gmask, best, m));

    // geometric wall bound for covered region = cells cx-1..cx+1, cy-1..cy+1
    float mb = __int_as_float(0x7f800000);
    if (cx - 1 > 0)     mb = fminf(mb, ax - (X0 + (float)(cx - 1) * H));
    if (cx + 1 < G - 1) mb = fminf(mb, (X0 + (float)(cx + 2) * H) - ax);
    if (cy - 1 > 0)     mb = fminf(mb, ay - (X0 + (float)(cy - 1) * H));
    if (cy + 1 < G - 1) mb = fminf(mb, (X0 + (float)(cy + 2) * H) - ay);

    float bd = __uint_as_float((unsigned)(best >> 32));
    bool need_fb = (best == 1ull) || !(bd <= mb - 1e-6f);

    // ---- exact fallback: expanding rings over CSR, from scratch ----
    if (need_fb) {
        best = 0xFFFFFFFFFFFFFFFFull;
        for (int r = 0; ; ++r) {
            if (r == 0) {
                if (lane == 0) csr_cell(cy * G + cx, ax, ay, best);
            } else {
                int nc = 8 * r;
                for (int tc = lane; tc < nc; tc += LPQ) {
                    int i, j;
                    if (tc < 2 * r + 1)      { i = cx - r + tc;               j = cy - r; }
                    else if (tc < 4 * r + 2) { i = cx - r + (tc - (2*r + 1)); j = cy + r; }
                    else { int s = tc - (4*r + 2); j = cy - r + 1 + (s >> 1);
                           i = (s & 1) ? cx + r : cx - r; }
                    if ((unsigned)i < G && (unsigned)j < G)
                        csr_cell(j * G + i, ax, ay, best);
                }
            }
            #pragma unroll
            for (int m = 4; m >= 1; m >>= 1)
                best = min(best, __shfl_xor_sync(gmask, best, m));

            // covered: cells cx-r..cx+r, cy-r..cy+r
            if (cx - r <= 0 && cx + r >= G - 1 &&
                cy - r <= 0 && cy + r >= G - 1) break;
            float m2 = __int_as_float(0x7f800000);
            if (cx - r > 0)     m2 = fminf(m2, ax - (X0 + (float)(cx - r) * H));
            if (cx + r < G - 1) m2 = fminf(m2, (X0 + (float)(cx + r + 1) * H) - ax);
            if (cy - r > 0)     m2 = fminf(m2, ay - (X0 + (float)(cy - r) * H));
            if (cy + r < G - 1) m2 = fminf(m2, (X0 + (float)(cy + r + 1) * H) - ay);
            float bd2 = __uint_as_float((unsigned)(best >> 32));
            if (bd2 <= m2 - 1e-6f) break;
        }
    }

    if (lane == 0) {
        unsigned pay = (unsigned)best;
        float4 pt = (pay & 0x80000u) ? __ldg(&g_pts[pay & 0x7FFFu])
                                     : __ldg(&g_slot[pay & 0x7FFFu]);
        ((float2*)out)[q] = make_float2(ax - pt.x, ay - pt.y);
    }
}

extern "C" void kernel_launch(void* const* d_in, const int* in_sizes, int n_in,
                              void* d_out, int out_size)
{
    const float* A = (const float*)d_in[0];   // [Q, 2]
    const float* B = (const float*)d_in[1];   // [2, N]
    float*     out = (float*)d_out;           // [Q, 2]

    const int Q = in_sizes[0] / 2;
    const int N = in_sizes[1] / 2;

    build_k<<<1, 1024>>>(B, N);
    query_k<<<(Q * LPQ + 255) / 256, 256>>>(A, out, Q);
}

// round 8
// speedup vs baseline: 1.4033x; 1.4033x over previous
#include <cuda_runtime.h>

// Exact L-inf nearest neighbor, 3 graph-captured kernels:
//   build_k : ONE block bins B into a CSR grid (smem count/scan/scatter),
//             zeroes the fail counter.
//   fast_k  : 4 lanes/query. Scans rings 0+1 as 3 contiguous CSR row spans,
//             points spread over lanes, u64 pack+min, 2-level shfl reduce.
//             Accepts iff best dist beats the geometric wall bound of the
//             3x3 region; otherwise pushes the query onto a fail list.
//   slow_k  : one FULL WARP per failed query; exact expanding Chebyshev
//             rings over the CSR with per-ring wall bounds.
// u64 pack (dist_bits<<32 | idx<<14 | pos): min() IS the lexicographic
// (d, idx) compare -> exact jnp.argmin first-index tie semantics.
// Wall-bound soundness: B points outside [X0,X0+EXT] are clamped into edge
// cells, so once the covered rectangle touches a grid edge that wall is
// dropped -- every unscanned point is strictly beyond a remaining wall.

#define G      64
#define NCELL  (G * G)
#define X0     (-4.5f)
#define EXT    9.0f
#define H      (EXT / (float)G)          // 0.140625, binary exact
#define INVH   ((float)G / EXT)
#define MAXPTS 16384
#define EPS    1e-6f

__device__ int    g_off[NCELL + 1];
__device__ float4 g_pts[MAXPTS];         // (x, y, idx_bits, 0)
__device__ int    g_fail_cnt;
__device__ int    g_fail[32768];

__device__ __forceinline__ int cell_coord(float v) {
    int c = __float2int_rd((v - X0) * INVH);
    return min(max(c, 0), G - 1);
}

// ---------------- build: one block ----------------
__global__ void __launch_bounds__(1024)
build_k(const float* __restrict__ B, int N)
{
    __shared__ int s_cnt[NCELL];
    __shared__ int s_off[NCELL];
    __shared__ int s_wsum[32];

    const int t = threadIdx.x;
    if (t == 0) g_fail_cnt = 0;
    for (int c = t; c < NCELL; c += 1024) s_cnt[c] = 0;
    __syncthreads();

    float px[4], py[4]; int pcell[4]; int np = 0;
    for (int n = t; n < N; n += 1024) {
        float x = B[n], y = B[N + n];
        int c = cell_coord(y) * G + cell_coord(x);
        px[np] = x; py[np] = y; pcell[np] = c; ++np;
        atomicAdd(&s_cnt[c], 1);
    }
    __syncthreads();

    const int base = t * (NCELL / 1024);
    int l0 = s_cnt[base+0], l1 = s_cnt[base+1], l2 = s_cnt[base+2], l3 = s_cnt[base+3];
    int tot = l0 + l1 + l2 + l3;
    const int lane = t & 31, wid = t >> 5;
    int v = tot;
    #pragma unroll
    for (int m = 1; m < 32; m <<= 1) {
        int u = __shfl_up_sync(0xffffffffu, v, m);
        if (lane >= m) v += u;
    }
    if (lane == 31) s_wsum[wid] = v;
    __syncthreads();
    if (wid == 0) {
        int w = s_wsum[lane];
        #pragma unroll
        for (int m = 1; m < 32; m <<= 1) {
            int u = __shfl_up_sync(0xffffffffu, w, m);
            if (lane >= m) w += u;
        }
        s_wsum[lane] = w;
    }
    __syncthreads();
    int excl = v - tot + (wid ? s_wsum[wid - 1] : 0);
    s_off[base+0] = excl;
    s_off[base+1] = excl + l0;
    s_off[base+2] = excl + l0 + l1;
    s_off[base+3] = excl + l0 + l1 + l2;
    s_cnt[base+0] = 0; s_cnt[base+1] = 0; s_cnt[base+2] = 0; s_cnt[base+3] = 0;
    __syncthreads();

    for (int c = t; c < NCELL; c += 1024) g_off[c] = s_off[c];
    if (t == 1023) g_off[NCELL] = excl + tot;

    for (int k = 0; k < np; ++k) {
        int c = pcell[k];
        int n = t + (k << 10);                // points strided n = t + 1024*k
        int pos = s_off[c] + atomicAdd(&s_cnt[c], 1);
        g_pts[pos] = make_float4(px[k], py[k], __int_as_float(n), 0.0f);
    }
}

// ---------------- shared helpers ----------------
__device__ __forceinline__ void scan_point(int p, float ax, float ay,
                                           unsigned long long& best)
{
    float4 pt = __ldg(&g_pts[p]);
    float dx = ax - pt.x, dy = ay - pt.y;
    float d  = fmaxf(fabsf(dx), fabsf(dy));
    unsigned pay = (__float_as_uint(pt.z) << 14) | (unsigned)p;
    unsigned long long c = (((unsigned long long)__float_as_uint(d)) << 32) | pay;
    best = min(best, c);
}

// ---------------- fast kernel: 4 lanes/query, no fallback code ----------------
__global__ void __launch_bounds__(256, 8)
fast_k(const float* __restrict__ A, float* __restrict__ out, int Q)
{
    const int tid  = blockIdx.x * 256 + threadIdx.x;
    const int q    = tid >> 2;
    const int lane = tid & 3;
    if (q >= Q) return;

    const unsigned gmask = 0xFu << (threadIdx.x & 28);

    const float ax = __ldg(&A[2 * q]);
    const float ay = __ldg(&A[2 * q + 1]);
    const int cx = cell_coord(ax);
    const int cy = cell_coord(ay);

    const int i0  = max(cx - 1, 0);
    const int i1p = min(cx + 1, G - 1) + 1;

    int s0 = 0, c0 = 0, s1, c1, s2 = 0, c2 = 0;
    if (cy - 1 >= 0) {
        int rb = (cy - 1) * G;
        s0 = __ldg(&g_off[rb + i0]); c0 = __ldg(&g_off[rb + i1p]) - s0;
    }
    {
        int rb = cy * G;
        s1 = __ldg(&g_off[rb + i0]); c1 = __ldg(&g_off[rb + i1p]) - s1;
    }
    if (cy + 1 <= G - 1) {
        int rb = (cy + 1) * G;
        s2 = __ldg(&g_off[rb + i0]); c2 = __ldg(&g_off[rb + i1p]) - s2;
    }

    unsigned long long best = 0xFFFFFFFFFFFFFFFFull;
    const int c01 = c0 + c1;
    const int T   = c01 + c2;
    for (int k = lane; k < T; k += 4) {
        int p = (k < c0) ? (s0 + k) : ((k < c01) ? (s1 + k - c0) : (s2 + k - c01));
        scan_point(p, ax, ay, best);
    }
    best = min(best, __shfl_xor_sync(gmask, best, 2));
    best = min(best, __shfl_xor_sync(gmask, best, 1));

    if (lane == 0) {
        // wall bound of covered rect = cells [cx-1,cx+1]x[cy-1,cy+1]
        float mb = __int_as_float(0x7f800000);
        if (cx - 1 > 0)     mb = fminf(mb, ax - (X0 + (float)(cx - 1) * H));
        if (cx + 1 < G - 1) mb = fminf(mb, (X0 + (float)(cx + 2) * H) - ax);
        if (cy - 1 > 0)     mb = fminf(mb, ay - (X0 + (float)(cy - 1) * H));
        if (cy + 1 < G - 1) mb = fminf(mb, (X0 + (float)(cy + 2) * H) - ay);

        float bd = __uint_as_float((unsigned)(best >> 32));
        if (bd <= mb - EPS) {
            float4 pt = __ldg(&g_pts[(unsigned)best & 0x3FFFu]);
            ((float2*)out)[q] = make_float2(ax - pt.x, ay - pt.y);
        } else {
            int slot = atomicAdd(&g_fail_cnt, 1);
            g_fail[slot] = q;
        }
    }
}

// ---------------- slow kernel: one warp per failed query ----------------
__global__ void __launch_bounds__(256)
slow_k(const float* __restrict__ A, float* __restrict__ out, int nwarps_total)
{
    const int wglob = blockIdx.x * 8 + (threadIdx.x >> 5);
    const int lane  = threadIdx.x & 31;
    const int cnt   = g_fail_cnt;

    for (int f = wglob; f < cnt; f += nwarps_total) {
        const int q = g_fail[f];
        const float ax = __ldg(&A[2 * q]);
        const float ay = __ldg(&A[2 * q + 1]);
        const int cx = cell_coord(ax);
        const int cy = cell_coord(ay);

        unsigned long long best = 0xFFFFFFFFFFFFFFFFull;
        for (int r = 0; ; ++r) {
            if (r == 0) {
                if (lane == 0) {
                    int c = cy * G + cx;
                    int s = __ldg(&g_off[c]), e = __ldg(&g_off[c + 1]);
                    for (int p = s; p < e; ++p) scan_point(p, ax, ay, best);
                }
            } else {
                int nc = 8 * r;
                for (int tc = lane; tc < nc; tc += 32) {
                    int i, j;
                    if (tc < 2 * r + 1)      { i = cx - r + tc;               j = cy - r; }
                    else if (tc < 4 * r + 2) { i = cx - r + (tc - (2*r + 1)); j = cy + r; }
                    else { int s = tc - (4*r + 2); j = cy - r + 1 + (s >> 1);
                           i = (s & 1) ? cx + r : cx - r; }
                    if ((unsigned)i < G && (unsigned)j < G) {
                        int c = j * G + i;
                        int s = __ldg(&g_off[c]), e = __ldg(&g_off[c + 1]);
                        for (int p = s; p < e; ++p) scan_point(p, ax, ay, best);
                    }
                }
            }
            #pragma unroll
            for (int m = 16; m >= 1; m >>= 1)
                best = min(best, __shfl_xor_sync(0xffffffffu, best, m));

            if (cx - r <= 0 && cx + r >= G - 1 &&
                cy - r <= 0 && cy + r >= G - 1) break;
            float mb = __int_as_float(0x7f800000);
            if (cx - r > 0)     mb = fminf(mb, ax - (X0 + (float)(cx - r) * H));
            if (cx + r < G - 1) mb = fminf(mb, (X0 + (float)(cx + r + 1) * H) - ax);
            if (cy - r > 0)     mb = fminf(mb, ay - (X0 + (float)(cy - r) * H));
            if (cy + r < G - 1) mb = fminf(mb, (X0 + (float)(cy + r + 1) * H) - ay);
            float bd = __uint_as_float((unsigned)(best >> 32));
            if (bd <= mb - EPS) break;
        }

        if (lane == 0) {
            float4 pt = __ldg(&g_pts[(unsigned)best & 0x3FFFu]);
            ((float2*)out)[q] = make_float2(ax - pt.x, ay - pt.y);
        }
    }
}

extern "C" void kernel_launch(void* const* d_in, const int* in_sizes, int n_in,
                              void* d_out, int out_size)
{
    const float* A = (const float*)d_in[0];   // [Q, 2]
    const float* B = (const float*)d_in[1];   // [2, N]
    float*     out = (float*)d_out;           // [Q, 2]

    const int Q = in_sizes[0] / 2;
    const int N = in_sizes[1] / 2;

    build_k<<<1, 1024>>>(B, N);

    fast_k<<<(Q * 4 + 255) / 256, 256>>>(A, out, Q);

    const int slow_blocks = 256;                       // 2048 warps, grid-stride
    slow_k<<<slow_blocks, 256>>>(A, out, slow_blocks * 8);
}